// round 13
// baseline (speedup 1.0000x reference)
#include <cuda_runtime.h>
#include <math.h>

// Problem constants
#define Bsz 8
#define Hn  32
#define Dm  4096
#define DHd 128
#define Lc  4095          // cached length
#define NSPLIT 16
#define CHUNK 256         // (Lc+1) / NSPLIT
#define BH (Bsz*Hn)       // 256
#define DV4 (Dm/4)        // 1024 (16-byte chunks per row)

// Device scratch (no allocations allowed anywhere)
__device__ float g_q[Bsz*Dm];
__device__ float g_k[Bsz*Dm];
__device__ float g_v[Bsz*Dm];
__device__ float g_attn[Bsz*Dm];
__device__ float g_pout[NSPLIT*BH*DHd];
__device__ float g_pm[NSPLIT*BH];
__device__ float g_ps[NSPLIT*BH];

// ---- low-level helpers -----------------------------------------------------
// 128-bit streaming load (evict-first): zero-reuse data must not evict x.
__device__ __forceinline__ ulonglong2 ldcs128(const void* p) {
    ulonglong2 v;
    asm("ld.global.cs.v2.u64 {%0,%1}, [%2];" : "=l"(v.x), "=l"(v.y) : "l"(p));
    return v;
}
// 128-bit read-only cached load (x vectors: 128 KB, heavy reuse).
__device__ __forceinline__ ulonglong2 ldg128(const void* p) {
    ulonglong2 v;
    asm("ld.global.nc.v2.u64 {%0,%1}, [%2];" : "=l"(v.x), "=l"(v.y) : "l"(p));
    return v;
}
// Packed dual-lane FMA (sm_100+): d.lo += a.lo*b.lo ; d.hi += a.hi*b.hi
__device__ __forceinline__ void ffma2(unsigned long long& d,
                                      unsigned long long a,
                                      unsigned long long b) {
    asm("fma.rn.f32x2 %0, %1, %2, %0;" : "+l"(d) : "l"(a), "l"(b));
}
__device__ __forceinline__ float2 unpack2(unsigned long long v) {
    float lo, hi;
    asm("mov.b64 {%0, %1}, %2;" : "=f"(lo), "=f"(hi) : "l"(v));
    return make_float2(lo, hi);
}
__device__ __forceinline__ float hsum_u64(unsigned long long p0,
                                          unsigned long long p1) {
    float2 a = unpack2(p0), b = unpack2(p1);
    return (a.x + a.y) + (b.x + b.y);
}

// ---------------------------------------------------------------------------
// GEMV core: 2 rows per warp, all 8 batches accumulated while each W row is
// streamed exactly once (128-bit, coalesced, evict-first). Packed f32x2 FMA
// keeps the FMA pipe at ~42%. 128 threads = 4 warps = 8 rows per block;
// launch_bounds(128,3) caps regs at 170 -> guaranteed >=3 blocks/SM.
// ---------------------------------------------------------------------------
__device__ __forceinline__ void gemv2_body(const float* __restrict__ x,
                                           const float* __restrict__ W,
                                           float* __restrict__ out,
                                           int row0) {
    int lane = threadIdx.x & 31;
    const ulonglong2* W0 = reinterpret_cast<const ulonglong2*>(W + (size_t)row0 * Dm);
    const ulonglong2* W1 = reinterpret_cast<const ulonglong2*>(W + (size_t)(row0 + 1) * Dm);
    const ulonglong2* x2 = reinterpret_cast<const ulonglong2*>(x);

    unsigned long long a0[Bsz][2], a1[Bsz][2];
#pragma unroll
    for (int b = 0; b < Bsz; b++) {
        a0[b][0] = 0ull; a0[b][1] = 0ull;
        a1[b][0] = 0ull; a1[b][1] = 0ull;
    }

#pragma unroll 2
    for (int i = lane; i < DV4; i += 32) {
        ulonglong2 w0 = ldcs128(W0 + i);
        ulonglong2 w1 = ldcs128(W1 + i);
#pragma unroll
        for (int b = 0; b < Bsz; b++) {
            ulonglong2 xv = ldg128(x2 + b * DV4 + i);
            ffma2(a0[b][0], w0.x, xv.x);
            ffma2(a0[b][1], w0.y, xv.y);
            ffma2(a1[b][0], w1.x, xv.x);
            ffma2(a1[b][1], w1.y, xv.y);
        }
    }
#pragma unroll
    for (int b = 0; b < Bsz; b++) {
        float s0 = hsum_u64(a0[b][0], a0[b][1]);
        float s1 = hsum_u64(a1[b][0], a1[b][1]);
#pragma unroll
        for (int off = 16; off; off >>= 1) {
            s0 += __shfl_xor_sync(0xffffffffu, s0, off);
            s1 += __shfl_xor_sync(0xffffffffu, s1, off);
        }
        if (lane == 0) {
            out[b * Dm + row0]     = s0;
            out[b * Dm + row0 + 1] = s1;
        }
    }
}

// Fused Q/K/V projection: blockIdx.y selects the matrix. grid (512, 3) x 128.
__global__ void __launch_bounds__(128, 3) gemv_qkv(const float* __restrict__ x,
                                                   const float* __restrict__ Wq,
                                                   const float* __restrict__ Wk,
                                                   const float* __restrict__ Wv) {
    int row0 = blockIdx.x * 8 + (threadIdx.x >> 5) * 2;
    const float* W;
    float* out;
    if (blockIdx.y == 0)      { W = Wq; out = g_q; }
    else if (blockIdx.y == 1) { W = Wk; out = g_k; }
    else                      { W = Wv; out = g_v; }
    gemv2_body(x, W, out, row0);
}

// Output projection: grid (512) x 128.
__global__ void __launch_bounds__(128, 3) gemv_o(const float* __restrict__ W,
                                                 float* __restrict__ out) {
    int row0 = blockIdx.x * 8 + (threadIdx.x >> 5) * 2;
    gemv2_body(g_attn, W, out, row0);
}

// ---------------------------------------------------------------------------
// Flash-decoding partial attention.
// blockIdx.x = bh*NSPLIT + s ; 256 threads (8 warps).
// Warp-per-key dot products; block softmax partials; partial V accumulation.
// Only split NSPLIT-1 contains the new token (position Lc) — epilogue path.
// ---------------------------------------------------------------------------
__global__ void __launch_bounds__(256) attn_partial(const float* __restrict__ kc,
                                                    const float* __restrict__ vc) {
    int s    = blockIdx.x & (NSPLIT - 1);
    int bh   = blockIdx.x / NSPLIT;
    int h    = bh & (Hn - 1);
    int b    = bh >> 5;
    int lane = threadIdx.x & 31;
    int warp = threadIdx.x >> 5;

    __shared__ float  sc[CHUNK];
    __shared__ float  red[8];
    __shared__ float4 wacc[8][32];

    const float4* q4p = reinterpret_cast<const float4*>(g_q + b * Dm + h * DHd);
    float4 q4 = q4p[lane];

    size_t base = (size_t)bh * Lc * DHd;
    const float4* K = reinterpret_cast<const float4*>(kc + base);
    const float4* V = reinterpret_cast<const float4*>(vc + base);
    int j0   = s * CHUNK;
    int jmax = (j0 + CHUNK <= Lc) ? CHUNK : (Lc - j0);   // 256, or 255 on last split

    // --- scores from cache ---
#pragma unroll 4
    for (int j = warp; j < jmax; j += 8) {
        float4 k4 = __ldcs(K + (size_t)(j0 + j) * (DHd/4) + lane);
        float d = q4.x*k4.x + q4.y*k4.y + q4.z*k4.z + q4.w*k4.w;
#pragma unroll
        for (int off = 16; off; off >>= 1)
            d += __shfl_xor_sync(0xffffffffu, d, off);
        if (lane == 0) sc[j] = d * 0.08838834764831845f;   // 1/sqrt(128)
    }
    // --- new token score (last split only; j = CHUNK-1 belongs to warp 7) ---
    if (jmax < CHUNK && warp == 7) {
        const float4* knew = reinterpret_cast<const float4*>(g_k + b * Dm + h * DHd);
        float4 k4 = knew[lane];
        float d = q4.x*k4.x + q4.y*k4.y + q4.z*k4.z + q4.w*k4.w;
#pragma unroll
        for (int off = 16; off; off >>= 1)
            d += __shfl_xor_sync(0xffffffffu, d, off);
        if (lane == 0) sc[CHUNK - 1] = d * 0.08838834764831845f;
    }
    __syncthreads();

    // --- block max (CHUNK == blockDim.x) ---
    float m = sc[threadIdx.x];
#pragma unroll
    for (int off = 16; off; off >>= 1)
        m = fmaxf(m, __shfl_xor_sync(0xffffffffu, m, off));
    if (lane == 0) red[warp] = m;
    __syncthreads();
    m = red[0];
#pragma unroll
    for (int w = 1; w < 8; w++) m = fmaxf(m, red[w]);
    __syncthreads();   // all reads of red done before reuse

    // --- exp + partial sum ---
    float e = __expf(sc[threadIdx.x] - m);
    sc[threadIdx.x] = e;
    float sum = e;
#pragma unroll
    for (int off = 16; off; off >>= 1)
        sum += __shfl_xor_sync(0xffffffffu, sum, off);
    if (lane == 0) red[warp] = sum;
    __syncthreads();   // sc[] updates + red[] visible to all
    sum = 0.f;
#pragma unroll
    for (int w = 0; w < 8; w++) sum += red[w];

    // --- weighted V accumulation ---
    float4 acc = make_float4(0.f, 0.f, 0.f, 0.f);
#pragma unroll 4
    for (int j = warp; j < jmax; j += 8) {
        float4 v4 = __ldcs(V + (size_t)(j0 + j) * (DHd/4) + lane);
        float p = sc[j];
        acc.x = fmaf(p, v4.x, acc.x);
        acc.y = fmaf(p, v4.y, acc.y);
        acc.z = fmaf(p, v4.z, acc.z);
        acc.w = fmaf(p, v4.w, acc.w);
    }
    if (jmax < CHUNK && warp == 7) {
        const float4* vnew = reinterpret_cast<const float4*>(g_v + b * Dm + h * DHd);
        float4 v4 = vnew[lane];
        float p = sc[CHUNK - 1];
        acc.x = fmaf(p, v4.x, acc.x);
        acc.y = fmaf(p, v4.y, acc.y);
        acc.z = fmaf(p, v4.z, acc.z);
        acc.w = fmaf(p, v4.w, acc.w);
    }
    wacc[warp][lane] = acc;
    __syncthreads();

    if (warp == 0) {
        float4 t = wacc[0][lane];
#pragma unroll
        for (int w = 1; w < 8; w++) {
            float4 u = wacc[w][lane];
            t.x += u.x; t.y += u.y; t.z += u.z; t.w += u.w;
        }
        reinterpret_cast<float4*>(g_pout + ((size_t)s * BH + bh) * DHd)[lane] = t;
        if (lane == 0) {
            g_pm[s * BH + bh] = m;
            g_ps[s * BH + bh] = sum;
        }
    }
}

// ---------------------------------------------------------------------------
// Combine NSPLIT partial softmax results per (b,h); write g_attn laid out as
// (B, H*DH) matching transpose(0,2,1,3).reshape(B,1,D).
// ---------------------------------------------------------------------------
__global__ void __launch_bounds__(128) attn_combine() {
    int bh = blockIdx.x;
    int t  = threadIdx.x;

    float pm[NSPLIT];
#pragma unroll
    for (int s = 0; s < NSPLIT; s++) pm[s] = g_pm[s * BH + bh];

    float m = pm[0];
#pragma unroll
    for (int s = 1; s < NSPLIT; s++) m = fmaxf(m, pm[s]);

    float denom = 0.f, acc = 0.f;
#pragma unroll
    for (int s = 0; s < NSPLIT; s++) {
        float w = __expf(pm[s] - m);
        denom += w * g_ps[s * BH + bh];
        acc   += w * g_pout[((size_t)s * BH + bh) * DHd + t];
    }
    int b = bh >> 5, h = bh & (Hn - 1);
    g_attn[b * Dm + h * DHd + t] = acc / denom;
}

// ---------------------------------------------------------------------------
// Launch.  Inputs (metadata order): x, key_cache, value_cache, Wq, Wk, Wv, Wo
// ---------------------------------------------------------------------------
extern "C" void kernel_launch(void* const* d_in, const int* in_sizes, int n_in,
                              void* d_out, int out_size) {
    const float* x  = (const float*)d_in[0];
    const float* kc = (const float*)d_in[1];
    const float* vc = (const float*)d_in[2];
    const float* Wq = (const float*)d_in[3];
    const float* Wk = (const float*)d_in[4];
    const float* Wv = (const float*)d_in[5];
    const float* Wo = (const float*)d_in[6];
    float* out = (float*)d_out;

    dim3 gqkv(Dm / 8, 3);
    gemv_qkv<<<gqkv, 128>>>(x, Wq, Wk, Wv);
    attn_partial<<<BH * NSPLIT, 256>>>(kc, vc);
    attn_combine<<<BH, 128>>>();
    gemv_o<<<Dm / 8, 128>>>(Wo, out);
}

// round 14
// speedup vs baseline: 1.0827x; 1.0827x over previous
#include <cuda_runtime.h>
#include <math.h>

// Problem constants
#define Bsz 8
#define Hn  32
#define Dm  4096
#define DHd 128
#define Lc  4095          // cached length
#define NSPLIT 16
#define CHUNK 256         // (Lc+1) / NSPLIT
#define BH (Bsz*Hn)       // 256
#define DV4 (Dm/4)        // 1024 (16-byte chunks per row)

// Device scratch (no allocations allowed anywhere)
__device__ float g_q[Bsz*Dm];
__device__ float g_k[Bsz*Dm];
__device__ float g_v[Bsz*Dm];
__device__ float g_attn[Bsz*Dm];
__device__ float g_pout[NSPLIT*BH*DHd];
__device__ float g_pm[NSPLIT*BH];
__device__ float g_ps[NSPLIT*BH];

// ---- low-level helpers -----------------------------------------------------
// 128-bit streaming load (evict-first): zero-reuse data must not evict x.
__device__ __forceinline__ ulonglong2 ldcs128(const void* p) {
    ulonglong2 v;
    asm("ld.global.cs.v2.u64 {%0,%1}, [%2];" : "=l"(v.x), "=l"(v.y) : "l"(p));
    return v;
}
// 128-bit read-only cached load (x vectors: 128 KB, heavy reuse).
__device__ __forceinline__ ulonglong2 ldg128(const void* p) {
    ulonglong2 v;
    asm("ld.global.nc.v2.u64 {%0,%1}, [%2];" : "=l"(v.x), "=l"(v.y) : "l"(p));
    return v;
}
// Packed dual-lane FMA (sm_100+): d.lo += a.lo*b.lo ; d.hi += a.hi*b.hi
__device__ __forceinline__ void ffma2(unsigned long long& d,
                                      unsigned long long a,
                                      unsigned long long b) {
    asm("fma.rn.f32x2 %0, %1, %2, %0;" : "+l"(d) : "l"(a), "l"(b));
}
__device__ __forceinline__ float2 unpack2(unsigned long long v) {
    float lo, hi;
    asm("mov.b64 {%0, %1}, %2;" : "=f"(lo), "=f"(hi) : "l"(v));
    return make_float2(lo, hi);
}

// ---------------------------------------------------------------------------
// GEMV core: 2 rows per warp, all 8 batches accumulated while each W row is
// streamed exactly once (128-bit, coalesced, evict-first).
// v2 (post-R13-ncu): ONE packed accumulator per (batch,row) — 16 u64 = 32 regs
// instead of 64 — plus unroll 4 for 8 outstanding W loads per warp and
// launch_bounds(128,4): the R13 profile showed occ=15.6%, DRAM=29.6% —
// latency-starved, not pipe-bound. 4 blocks/SM doubles latency hiding.
// ---------------------------------------------------------------------------
__device__ __forceinline__ void gemv2_body(const float* __restrict__ x,
                                           const float* __restrict__ W,
                                           float* __restrict__ out,
                                           int row0) {
    int lane = threadIdx.x & 31;
    const ulonglong2* W0 = reinterpret_cast<const ulonglong2*>(W + (size_t)row0 * Dm);
    const ulonglong2* W1 = reinterpret_cast<const ulonglong2*>(W + (size_t)(row0 + 1) * Dm);
    const ulonglong2* x2 = reinterpret_cast<const ulonglong2*>(x);

    unsigned long long a0[Bsz], a1[Bsz];
#pragma unroll
    for (int b = 0; b < Bsz; b++) { a0[b] = 0ull; a1[b] = 0ull; }

#pragma unroll 4
    for (int i = lane; i < DV4; i += 32) {
        ulonglong2 w0 = ldcs128(W0 + i);
        ulonglong2 w1 = ldcs128(W1 + i);
#pragma unroll
        for (int b = 0; b < Bsz; b++) {
            ulonglong2 xv = ldg128(x2 + b * DV4 + i);
            ffma2(a0[b], w0.x, xv.x);
            ffma2(a0[b], w0.y, xv.y);
            ffma2(a1[b], w1.x, xv.x);
            ffma2(a1[b], w1.y, xv.y);
        }
    }
#pragma unroll
    for (int b = 0; b < Bsz; b++) {
        float2 p0 = unpack2(a0[b]);
        float2 p1 = unpack2(a1[b]);
        float s0 = p0.x + p0.y;
        float s1 = p1.x + p1.y;
#pragma unroll
        for (int off = 16; off; off >>= 1) {
            s0 += __shfl_xor_sync(0xffffffffu, s0, off);
            s1 += __shfl_xor_sync(0xffffffffu, s1, off);
        }
        if (lane == 0) {
            out[b * Dm + row0]     = s0;
            out[b * Dm + row0 + 1] = s1;
        }
    }
}

// Fused Q/K/V projection: blockIdx.y selects the matrix. grid (512, 3) x 128.
__global__ void __launch_bounds__(128, 4) gemv_qkv(const float* __restrict__ x,
                                                   const float* __restrict__ Wq,
                                                   const float* __restrict__ Wk,
                                                   const float* __restrict__ Wv) {
    int row0 = blockIdx.x * 8 + (threadIdx.x >> 5) * 2;
    const float* W;
    float* out;
    if (blockIdx.y == 0)      { W = Wq; out = g_q; }
    else if (blockIdx.y == 1) { W = Wk; out = g_k; }
    else                      { W = Wv; out = g_v; }
    gemv2_body(x, W, out, row0);
}

// Output projection: grid (512) x 128.
__global__ void __launch_bounds__(128, 4) gemv_o(const float* __restrict__ W,
                                                 float* __restrict__ out) {
    int row0 = blockIdx.x * 8 + (threadIdx.x >> 5) * 2;
    gemv2_body(g_attn, W, out, row0);
}

// ---------------------------------------------------------------------------
// Flash-decoding partial attention (UNCHANGED — running at the HBM roofline
// per the R13 wall-time decomposition).
// blockIdx.x = bh*NSPLIT + s ; 256 threads (8 warps).
// ---------------------------------------------------------------------------
__global__ void __launch_bounds__(256) attn_partial(const float* __restrict__ kc,
                                                    const float* __restrict__ vc) {
    int s    = blockIdx.x & (NSPLIT - 1);
    int bh   = blockIdx.x / NSPLIT;
    int h    = bh & (Hn - 1);
    int b    = bh >> 5;
    int lane = threadIdx.x & 31;
    int warp = threadIdx.x >> 5;

    __shared__ float  sc[CHUNK];
    __shared__ float  red[8];
    __shared__ float4 wacc[8][32];

    const float4* q4p = reinterpret_cast<const float4*>(g_q + b * Dm + h * DHd);
    float4 q4 = q4p[lane];

    size_t base = (size_t)bh * Lc * DHd;
    const float4* K = reinterpret_cast<const float4*>(kc + base);
    const float4* V = reinterpret_cast<const float4*>(vc + base);
    int j0   = s * CHUNK;
    int jmax = (j0 + CHUNK <= Lc) ? CHUNK : (Lc - j0);   // 256, or 255 on last split

    // --- scores from cache ---
#pragma unroll 4
    for (int j = warp; j < jmax; j += 8) {
        float4 k4 = __ldcs(K + (size_t)(j0 + j) * (DHd/4) + lane);
        float d = q4.x*k4.x + q4.y*k4.y + q4.z*k4.z + q4.w*k4.w;
#pragma unroll
        for (int off = 16; off; off >>= 1)
            d += __shfl_xor_sync(0xffffffffu, d, off);
        if (lane == 0) sc[j] = d * 0.08838834764831845f;   // 1/sqrt(128)
    }
    // --- new token score (last split only; j = CHUNK-1 belongs to warp 7) ---
    if (jmax < CHUNK && warp == 7) {
        const float4* knew = reinterpret_cast<const float4*>(g_k + b * Dm + h * DHd);
        float4 k4 = knew[lane];
        float d = q4.x*k4.x + q4.y*k4.y + q4.z*k4.z + q4.w*k4.w;
#pragma unroll
        for (int off = 16; off; off >>= 1)
            d += __shfl_xor_sync(0xffffffffu, d, off);
        if (lane == 0) sc[CHUNK - 1] = d * 0.08838834764831845f;
    }
    __syncthreads();

    // --- block max (CHUNK == blockDim.x) ---
    float m = sc[threadIdx.x];
#pragma unroll
    for (int off = 16; off; off >>= 1)
        m = fmaxf(m, __shfl_xor_sync(0xffffffffu, m, off));
    if (lane == 0) red[warp] = m;
    __syncthreads();
    m = red[0];
#pragma unroll
    for (int w = 1; w < 8; w++) m = fmaxf(m, red[w]);
    __syncthreads();   // all reads of red done before reuse

    // --- exp + partial sum ---
    float e = __expf(sc[threadIdx.x] - m);
    sc[threadIdx.x] = e;
    float sum = e;
#pragma unroll
    for (int off = 16; off; off >>= 1)
        sum += __shfl_xor_sync(0xffffffffu, sum, off);
    if (lane == 0) red[warp] = sum;
    __syncthreads();   // sc[] updates + red[] visible to all
    sum = 0.f;
#pragma unroll
    for (int w = 0; w < 8; w++) sum += red[w];

    // --- weighted V accumulation ---
    float4 acc = make_float4(0.f, 0.f, 0.f, 0.f);
#pragma unroll 4
    for (int j = warp; j < jmax; j += 8) {
        float4 v4 = __ldcs(V + (size_t)(j0 + j) * (DHd/4) + lane);
        float p = sc[j];
        acc.x = fmaf(p, v4.x, acc.x);
        acc.y = fmaf(p, v4.y, acc.y);
        acc.z = fmaf(p, v4.z, acc.z);
        acc.w = fmaf(p, v4.w, acc.w);
    }
    if (jmax < CHUNK && warp == 7) {
        const float4* vnew = reinterpret_cast<const float4*>(g_v + b * Dm + h * DHd);
        float4 v4 = vnew[lane];
        float p = sc[CHUNK - 1];
        acc.x = fmaf(p, v4.x, acc.x);
        acc.y = fmaf(p, v4.y, acc.y);
        acc.z = fmaf(p, v4.z, acc.z);
        acc.w = fmaf(p, v4.w, acc.w);
    }
    wacc[warp][lane] = acc;
    __syncthreads();

    if (warp == 0) {
        float4 t = wacc[0][lane];
#pragma unroll
        for (int w = 1; w < 8; w++) {
            float4 u = wacc[w][lane];
            t.x += u.x; t.y += u.y; t.z += u.z; t.w += u.w;
        }
        reinterpret_cast<float4*>(g_pout + ((size_t)s * BH + bh) * DHd)[lane] = t;
        if (lane == 0) {
            g_pm[s * BH + bh] = m;
            g_ps[s * BH + bh] = sum;
        }
    }
}

// ---------------------------------------------------------------------------
// Combine NSPLIT partial softmax results per (b,h); write g_attn laid out as
// (B, H*DH) matching transpose(0,2,1,3).reshape(B,1,D).
// ---------------------------------------------------------------------------
__global__ void __launch_bounds__(128) attn_combine() {
    int bh = blockIdx.x;
    int t  = threadIdx.x;

    float pm[NSPLIT];
#pragma unroll
    for (int s = 0; s < NSPLIT; s++) pm[s] = g_pm[s * BH + bh];

    float m = pm[0];
#pragma unroll
    for (int s = 1; s < NSPLIT; s++) m = fmaxf(m, pm[s]);

    float denom = 0.f, acc = 0.f;
#pragma unroll
    for (int s = 0; s < NSPLIT; s++) {
        float w = __expf(pm[s] - m);
        denom += w * g_ps[s * BH + bh];
        acc   += w * g_pout[((size_t)s * BH + bh) * DHd + t];
    }
    int b = bh >> 5, h = bh & (Hn - 1);
    g_attn[b * Dm + h * DHd + t] = acc / denom;
}

// ---------------------------------------------------------------------------
// Launch.  Inputs (metadata order): x, key_cache, value_cache, Wq, Wk, Wv, Wo
// ---------------------------------------------------------------------------
extern "C" void kernel_launch(void* const* d_in, const int* in_sizes, int n_in,
                              void* d_out, int out_size) {
    const float* x  = (const float*)d_in[0];
    const float* kc = (const float*)d_in[1];
    const float* vc = (const float*)d_in[2];
    const float* Wq = (const float*)d_in[3];
    const float* Wk = (const float*)d_in[4];
    const float* Wv = (const float*)d_in[5];
    const float* Wo = (const float*)d_in[6];
    float* out = (float*)d_out;

    dim3 gqkv(Dm / 8, 3);
    gemv_qkv<<<gqkv, 128>>>(x, Wq, Wk, Wv);
    attn_partial<<<BH * NSPLIT, 256>>>(kc, vc);
    attn_combine<<<BH, 128>>>();
    gemv_o<<<Dm / 8, 128>>>(Wo, out);
}